// round 12
// baseline (speedup 1.0000x reference)
#include <cuda_runtime.h>
#include <cuda_fp16.h>
#include <cuda_bf16.h>

// Fixed problem shapes:
//   tex (8,16,512,512) f32, iuv (8,3,512,512) i32, lut (24,256,256,2) f32,
//   tex_res = 512 (1-element i32 device scalar), out (8,16,512,512) f32.
#define BB 8
#define CC 16
#define RR 512
#define RR2 (RR * RR)        // 2^18
#define HW  (512 * 512)      // 2^18
#define LOG2_RR2 18
#define LOG2_HW  18

// FULL transposed texture in fp16: [b][pixel][channel] = 64 MiB.
// 32B per pixel; 256B-aligned so LDG.256 gathers are legal.
__device__ __align__(256) __half g_scratch[(size_t)BB * RR2 * CC];

// 256-bit global load (sm_100+): one LDG.E.256.
__device__ __forceinline__ void ldg256(const void* p, unsigned int w[8]) {
    asm("ld.global.v8.u32 {%0,%1,%2,%3,%4,%5,%6,%7}, [%8];"
        : "=r"(w[0]), "=r"(w[1]), "=r"(w[2]), "=r"(w[3]),
          "=r"(w[4]), "=r"(w[5]), "=r"(w[6]), "=r"(w[7])
        : "l"(p));
}
// 256-bit streaming (evict-first) global load.
__device__ __forceinline__ void ldg256_cs(const void* p, float f[8]) {
    asm("ld.global.cs.v8.f32 {%0,%1,%2,%3,%4,%5,%6,%7}, [%8];"
        : "=f"(f[0]), "=f"(f[1]), "=f"(f[2]), "=f"(f[3]),
          "=f"(f[4]), "=f"(f[5]), "=f"(f[6]), "=f"(f[7])
        : "l"(p));
}

// ---------------------------------------------------------------------------
// Transpose: (B,C,R,R) f32 -> scratch (B,R*R,C) fp16.
// One thread = 4 channels x 8 consecutive pixels:
//   4 x LDG.256 (warp per channel = 1KB contiguous) -> 2x the in-flight
//   bytes of the R10 body; 8 x 8B stores (lanes c4=0..3 cover one pixel's
//   32B contiguously), same proven store pattern.
// ---------------------------------------------------------------------------
__global__ void __launch_bounds__(256) transpose_kernel(
    const float* __restrict__ tex)
{
    int idx = blockIdx.x * blockDim.x + threadIdx.x;   // [0, BB*RR2/2)
    int c4 = idx & 3;                                   // channel group 0..3
    int p8 = ((idx >> 2) & (RR2 / 8 - 1)) * 8;          // first of 8 pixels
    int b  = idx >> (LOG2_RR2 - 1);                     // batch

    const float* src = tex + ((size_t)b * CC + (size_t)c4 * 4) * RR2 + p8;
    float f0[8], f1[8], f2[8], f3[8];
    ldg256_cs(src + 0 * RR2, f0);
    ldg256_cs(src + 1 * RR2, f1);
    ldg256_cs(src + 2 * RR2, f2);
    ldg256_cs(src + 3 * RR2, f3);

    __half* dst = g_scratch + ((size_t)b * RR2 + p8) * CC + (size_t)c4 * 4;
    #pragma unroll
    for (int j = 0; j < 8; j++) {                       // pixel within octet
        __half2 h0 = __floats2half2_rn(f0[j], f1[j]);
        __half2 h1 = __floats2half2_rn(f2[j], f3[j]);
        uint2 w;
        w.x = *reinterpret_cast<const unsigned int*>(&h0);
        w.y = *reinterpret_cast<const unsigned int*>(&h1);
        *reinterpret_cast<uint2*>(dst + (size_t)j * CC) = w;
    }
}

// ---------------------------------------------------------------------------
// Gather: one thread per (b, pixel), ONE launch over all batches.
// 16 channels = 32 contiguous bytes fetched with a single LDG.256
// (halves the gather's L1 wavefronts vs 2 x LDG.128). Output write-through.
// Index math bit-identical to the R8/R11 winner.
// ---------------------------------------------------------------------------
__global__ void __launch_bounds__(256) densepose_kernel(
    const int*   __restrict__ iuv,
    const float* __restrict__ lut,
    const int*   __restrict__ tex_res_ptr,
    float*       __restrict__ out)
{
    int idx = blockIdx.x * blockDim.x + threadIdx.x;   // [0, BB*HW)
    int pix = idx & (HW - 1);
    int b   = idx >> LOG2_HW;

    const int* iuvb = iuv + (size_t)b * 3 * HW + pix;
    int part = __ldcs(iuvb);

    float r[16];
    #pragma unroll
    for (int c = 0; c < 16; c++) r[c] = 0.f;

    if (part > 0) {
        // Exact shortcut: round(clip(n/255)*255) == n for n in [0,255].
        int ui = min(max(__ldcs(iuvb + 1 * HW), 0), 255);
        int vi = min(max(__ldcs(iuvb + 2 * HW), 0), 255);
        int i  = min(max(part - 1, 0), 23);

        float2 uv = __ldg(reinterpret_cast<const float2*>(lut)
                          + ((size_t)i * 256 + vi) * 256 + ui);

        float resm1 = (float)(__ldg(tex_res_ptr) - 1);
        int u_I = min(max(__float2int_rn(uv.x * resm1), 0), RR - 1);
        int v_I = min(max(__float2int_rn((1.0f - uv.y) * resm1), 0), RR - 1);

        unsigned int w[8];
        ldg256(g_scratch + ((size_t)b * RR2 + (size_t)v_I * RR + u_I) * 16, w);

        #pragma unroll
        for (int j = 0; j < 8; j++) {
            __half2 h = *reinterpret_cast<const __half2*>(&w[j]);
            float2 f = __half22float2(h);
            r[2 * j]     = f.x;
            r[2 * j + 1] = f.y;
        }
    }

    // Output (B,C,H,W): 16 fully-coalesced scalar stores, write-through.
    float* o = out + (size_t)b * CC * HW + pix;
    #pragma unroll
    for (int c = 0; c < 16; c++)
        __stwt(o + (size_t)c * HW, r[c]);
}

extern "C" void kernel_launch(void* const* d_in, const int* in_sizes, int n_in,
                              void* d_out, int out_size)
{
    const float* tex     = (const float*)d_in[0];
    const int*   iuv     = (const int*)  d_in[1];
    const float* lut     = (const float*)d_in[2];
    const int*   tex_res = (const int*)  d_in[3];
    float* out = (float*)d_out;

    transpose_kernel<<<(BB * RR2 / 2) / 256, 256>>>(tex);      // 4096 blocks
    densepose_kernel<<<(BB * HW) / 256, 256>>>(iuv, lut, tex_res, out);
}